// round 16
// baseline (speedup 1.0000x reference)
#include <cuda_runtime.h>
#include <cuda_fp16.h>
#include <math.h>
#include <stdint.h>

constexpr int B_=16, N_=1024, CIN_=64, HID_=128, H_=8, COUT_=64, CAT_=HID_*H_;
typedef unsigned long long ull;

// device scratch (no allocation allowed)
__device__ __half g_ka[(size_t)B_*H_*N_*HID_];   // L1 feature limb hi, [bh][n][d]
__device__ __half g_kb[(size_t)B_*H_*N_*HID_];   // L1 feature limb lo
__device__ __half g_ca[(size_t)B_*N_*CAT_];      // L1 activated output limb hi, [b][n][hd]
__device__ __half g_cb[(size_t)B_*N_*CAT_];      // L1 activated output limb lo
__device__ __half g_wa[CAT_*COUT_];              // W_out limb hi [k][n]
__device__ __half g_wb[CAT_*COUT_];              // W_out limb lo
__device__ __half g_ha[(size_t)B_*N_*COUT_];     // L2 feature limb hi
__device__ __half g_hb[(size_t)B_*N_*COUT_];     // L2 feature limb lo
__device__ uint32_t g_bits[N_*(N_/32)];          // adjacency bitmask

// ---- f32x2 helpers ----
__device__ __forceinline__ ull f2pack(float lo, float hi){ ull r; asm("mov.b64 %0, {%1, %2};" : "=l"(r) : "f"(lo), "f"(hi)); return r; }
__device__ __forceinline__ float2 f2unpack(ull v){ float2 r; asm("mov.b64 {%0, %1}, %2;" : "=f"(r.x), "=f"(r.y) : "l"(v)); return r; }
__device__ __forceinline__ ull ffma2(ull a, ull b, ull c){ ull d; asm("fma.rn.f32x2 %0, %1, %2, %3;" : "=l"(d) : "l"(a), "l"(b), "l"(c)); return d; }

__device__ __forceinline__ uint32_t smem_u32(const void* p){ uint32_t a; asm("{ .reg .u64 t; cvta.to.shared.u64 t, %1; cvt.u32.u64 %0, t; }" : "=r"(a) : "l"(p)); return a; }

// ---- baseline-PTX tensor + async ops (compute_103-safe) ----
__device__ __forceinline__ void ldsm4(uint32_t& r0, uint32_t& r1, uint32_t& r2, uint32_t& r3, uint32_t addr){
    asm volatile("ldmatrix.sync.aligned.m8n8.x4.shared.b16 {%0,%1,%2,%3}, [%4];"
        : "=r"(r0), "=r"(r1), "=r"(r2), "=r"(r3) : "r"(addr));
}
__device__ __forceinline__ void ldsm4t(uint32_t& r0, uint32_t& r1, uint32_t& r2, uint32_t& r3, uint32_t addr){
    asm volatile("ldmatrix.sync.aligned.m8n8.x4.trans.shared.b16 {%0,%1,%2,%3}, [%4];"
        : "=r"(r0), "=r"(r1), "=r"(r2), "=r"(r3) : "r"(addr));
}
__device__ __forceinline__ void mma16816(float* c, const uint32_t* a, uint32_t b0, uint32_t b1){
    asm volatile("mma.sync.aligned.m16n8k16.row.col.f32.f16.f16.f32 "
        "{%0,%1,%2,%3}, {%4,%5,%6,%7}, {%8,%9}, {%0,%1,%2,%3};"
        : "+f"(c[0]), "+f"(c[1]), "+f"(c[2]), "+f"(c[3])
        : "r"(a[0]), "r"(a[1]), "r"(a[2]), "r"(a[3]), "r"(b0), "r"(b1));
}
__device__ __forceinline__ void hsplit2(float x, float y, uint32_t& a, uint32_t& b){
    __half hx = __float2half_rn(x), hy = __float2half_rn(y);
    float rx = x - __half2float(hx), ry = y - __half2float(hy);
    __half lx = __float2half_rn(rx), ly = __float2half_rn(ry);
    a = ((uint32_t)__half_as_ushort(hy) << 16) | (uint32_t)__half_as_ushort(hx);
    b = ((uint32_t)__half_as_ushort(ly) << 16) | (uint32_t)__half_as_ushort(lx);
}
__device__ __forceinline__ void cpa16(uint32_t saddr, const void* g){
    asm volatile("cp.async.cg.shared.global [%0], [%1], 16;" :: "r"(saddr), "l"(g));
}
#define CPA_COMMIT() asm volatile("cp.async.commit_group;" ::: "memory")
#define CPA_WAIT(n)  asm volatile("cp.async.wait_group %0;" :: "n"(n) : "memory")

// graph -> bitmask
__global__ __launch_bounds__(256) void graph_bits_kernel(const float* __restrict__ graph){
    int w = blockIdx.x*256 + threadIdx.x;
    int row = w >> 5, c0 = (w & 31) * 32;
    uint32_t bits = 0;
#pragma unroll 8
    for (int j = 0; j < 32; j++)
        bits |= (graph[(size_t)row*N_ + c0 + j] != 0.f ? 1u : 0u) << j;
    g_bits[w] = bits;
}

// W_out -> fp16 limbs
__global__ __launch_bounds__(256) void wsplit_kernel(const float* __restrict__ Wout){
    int i = blockIdx.x*256 + threadIdx.x;   // 32768 pairs
    float2 v = *(const float2*)(Wout + i*2);
    uint32_t a, b;
    hsplit2(v.x, v.y, a, b);
    *(uint32_t*)(g_wa + i*2) = a;
    *(uint32_t*)(g_wb + i*2) = b;
}

// gemm1: per-head GEMM, epilogue splits features into fp16 2-limb arrays [bh][n][d]
__global__ __launch_bounds__(256) void gemm1_kernel(const float* __restrict__ x,
                                                    const float* __restrict__ Wh){
    __shared__ float sX[64*CIN_];
    __shared__ float sW[CIN_*HID_];
    const int tid = threadIdx.x, tx = tid & 15, ty = tid >> 4;
    const int bn0 = blockIdx.x * 64, h = blockIdx.y;
    const float* Wp = Wh + (size_t)h*CIN_*HID_;

    for (int i = tid; i < CIN_*HID_/4; i += 256)
        *(float4*)(sW + i*4) = *(const float4*)(Wp + i*4);
    for (int i = tid; i < 64*CIN_/4; i += 256){
        int r = i >> 4, c4 = i & 15;
        *(float4*)(sX + r*CIN_ + c4*4) = *(const float4*)(x + (size_t)(bn0+r)*CIN_ + c4*4);
    }
    __syncthreads();

    ull a2[4][4];
#pragma unroll
    for (int i = 0; i < 4; i++)
#pragma unroll
        for (int j = 0; j < 4; j++) a2[i][j] = 0ull;
#pragma unroll 4
    for (int k4 = 0; k4 < CIN_; k4 += 4){
        float4 av[4];
#pragma unroll
        for (int i = 0; i < 4; i++) av[i] = *(const float4*)(sX + (ty*4+i)*CIN_ + k4);
#pragma unroll
        for (int k = 0; k < 4; k++){
            ulonglong2 wv[2];
#pragma unroll
            for (int g = 0; g < 2; g++) wv[g] = *(const ulonglong2*)(sW + (k4+k)*HID_ + 64*g + 4*tx);
#pragma unroll
            for (int i = 0; i < 4; i++){
                float a = ((const float*)&av[i])[k];
                ull pp = f2pack(a, a);
#pragma unroll
                for (int g = 0; g < 2; g++){
                    a2[i][g*2+0] = ffma2(pp, wv[g].x, a2[i][g*2+0]);
                    a2[i][g*2+1] = ffma2(pp, wv[g].y, a2[i][g*2+1]);
                }
            }
        }
    }
#pragma unroll
    for (int i = 0; i < 4; i++){
        const int bn = bn0 + ty*4 + i, bb = bn >> 10, nn = bn & 1023;
        const size_t base = ((size_t)(bb*H_+h)*N_ + nn)*HID_;
#pragma unroll
        for (int g = 0; g < 2; g++){
            float2 e0 = f2unpack(a2[i][g*2+0]), e1 = f2unpack(a2[i][g*2+1]);
            uint32_t pa0, pb0, pa1, pb1;
            hsplit2(e0.x, e0.y, pa0, pb0);
            hsplit2(e1.x, e1.y, pa1, pb1);
            size_t ki = base + 64*g + 4*tx;
            *(uint2*)(g_ka + ki) = make_uint2(pa0, pa1);
            *(uint2*)(g_kb + ki) = make_uint2(pb0, pb1);
        }
    }
}

// ---------------------------------------------------------------------------
// Unified fp16 2-limb emulated-fp32 flash attention via mma.sync.
// QROWS q-rows per CTA, QROWS/16 warps. kv tiles of 64, cp.async double-buffer.
// ---------------------------------------------------------------------------
template <int D, int LAYER, int QROWS>
__global__ __launch_bounds__(QROWS*2, 1) void attn_mma(const float* __restrict__ bias_g,
                                                       float* __restrict__ out2){
    constexpr int THREADS = QROWS*2;
    constexpr int KT = D / 16;
    constexpr int NO = D / 8;
    constexpr int CH = D / 8;
    constexpr int LDRB = (D + 8) * 2;
    constexpr int QLIMB = QROWS * LDRB;
    constexpr int KLIMB = 64 * LDRB;
    constexpr int KBUF = 2 * KLIMB;
    constexpr int OFF_K = 2 * QLIMB;

    extern __shared__ char sm[];
    const uint32_t sb = smem_u32(sm);
    const int tid = threadIdx.x, w = tid >> 5, lane = tid & 31;
    const int n0q = blockIdx.x * QROWS, b = blockIdx.y, h = blockIdx.z;
    const __half* Fa;
    const __half* Fb;
    if (LAYER == 1){
        const size_t bhoff = (size_t)(b*H_ + h);
        Fa = g_ka + bhoff*N_*HID_;
        Fb = g_kb + bhoff*N_*HID_;
    } else {
        Fa = g_ha + (size_t)b*N_*COUT_;
        Fb = g_hb + (size_t)b*N_*COUT_;
    }

    // stage Q
    for (int i = tid; i < QROWS*CH; i += THREADS){
        int r = i / CH, ch = i % CH;
        *(uint4*)(sm + 0     + r*LDRB + ch*16) = *(const uint4*)(Fa + (size_t)(n0q+r)*D + ch*8);
        *(uint4*)(sm + QLIMB + r*LDRB + ch*16) = *(const uint4*)(Fb + (size_t)(n0q+r)*D + ch*8);
    }
    __syncthreads();

    uint32_t qa[KT][4], qb[KT][4];
    {
        const int rowA = w*16 + (lane & 15);
        const int colA = (lane >> 4) * 8;
#pragma unroll
        for (int kt = 0; kt < KT; kt++){
            ldsm4(qa[kt][0], qa[kt][1], qa[kt][2], qa[kt][3], sb + 0     + rowA*LDRB + (kt*16 + colA)*2);
            ldsm4(qb[kt][0], qb[kt][1], qb[kt][2], qb[kt][3], sb + QLIMB + rowA*LDRB + (kt*16 + colA)*2);
        }
    }

    float o[NO][4];
#pragma unroll
    for (int i = 0; i < NO; i++){ o[i][0]=0.f; o[i][1]=0.f; o[i][2]=0.f; o[i][3]=0.f; }
    float m0r = -INFINITY, m1r = -INFINITY, l0 = 0.f, l1 = 0.f;

    const int g = lane >> 2, q4 = lane & 3;
    const int row0 = n0q + w*16 + g;

    for (int i = tid; i < 64*CH; i += THREADS){
        int r = i / CH, ch = i % CH;
        cpa16(sb + OFF_K + r*LDRB + ch*16,         Fa + (size_t)r*D + ch*8);
        cpa16(sb + OFF_K + KLIMB + r*LDRB + ch*16, Fb + (size_t)r*D + ch*8);
    }
    CPA_COMMIT();

    for (int t = 0; t < 16; t++){
        const uint32_t kbase = sb + OFF_K + (t & 1)*KBUF;
        if (t < 15){
            const int m1 = (t+1)*64;
            const uint32_t nb = sb + OFF_K + ((t+1) & 1)*KBUF;
            for (int i = tid; i < 64*CH; i += THREADS){
                int r = i / CH, ch = i % CH;
                cpa16(nb + r*LDRB + ch*16,         Fa + (size_t)(m1+r)*D + ch*8);
                cpa16(nb + KLIMB + r*LDRB + ch*16, Fb + (size_t)(m1+r)*D + ch*8);
            }
            CPA_COMMIT();
            CPA_WAIT(1);
        } else {
            CPA_WAIT(0);
        }
        __syncthreads();

        uint2 gb0 = *(const uint2*)&g_bits[(size_t)row0*32 + t*2];
        uint2 gb1 = *(const uint2*)&g_bits[(size_t)(row0+8)*32 + t*2];

        float s[8][4];
#pragma unroll
        for (int nt = 0; nt < 8; nt++){ s[nt][0]=0.f; s[nt][1]=0.f; s[nt][2]=0.f; s[nt][3]=0.f; }
        const int rowB = (lane & 7);
        const int colB8 = (lane >> 3) * 8;
#pragma unroll
        for (int nt = 0; nt < 8; nt++){
#pragma unroll
            for (int ktp = 0; ktp < KT/2; ktp++){
                uint32_t ka0, ka1, ka2, ka3, kb0, kb1, kb2, kb3;
                ldsm4(ka0, ka1, ka2, ka3, kbase + (nt*8 + rowB)*LDRB + (ktp*32 + colB8)*2);
                ldsm4(kb0, kb1, kb2, kb3, kbase + KLIMB + (nt*8 + rowB)*LDRB + (ktp*32 + colB8)*2);
                const int kt = 2*ktp;
                mma16816(s[nt], qa[kt],   ka0, ka1);
                mma16816(s[nt], qa[kt],   kb0, kb1);
                mma16816(s[nt], qb[kt],   ka0, ka1);
                mma16816(s[nt], qa[kt+1], ka2, ka3);
                mma16816(s[nt], qa[kt+1], kb2, kb3);
                mma16816(s[nt], qb[kt+1], ka2, ka3);
            }
        }

        float tm0 = -INFINITY, tm1 = -INFINITY;
#pragma unroll
        for (int nt = 0; nt < 8; nt++){
            int c0 = nt*8 + 2*q4, c1 = c0 + 1;
            uint32_t w00 = (c0 < 32) ? gb0.x : gb0.y;
            uint32_t w10 = (c0 < 32) ? gb1.x : gb1.y;
            if (!((w00 >> (c0 & 31)) & 1u)) s[nt][0] = -1e16f;
            if (!((w00 >> (c1 & 31)) & 1u)) s[nt][1] = -1e16f;
            if (!((w10 >> (c0 & 31)) & 1u)) s[nt][2] = -1e16f;
            if (!((w10 >> (c1 & 31)) & 1u)) s[nt][3] = -1e16f;
            tm0 = fmaxf(tm0, fmaxf(s[nt][0], s[nt][1]));
            tm1 = fmaxf(tm1, fmaxf(s[nt][2], s[nt][3]));
        }
        tm0 = fmaxf(tm0, __shfl_xor_sync(0xffffffffu, tm0, 1));
        tm0 = fmaxf(tm0, __shfl_xor_sync(0xffffffffu, tm0, 2));
        tm1 = fmaxf(tm1, __shfl_xor_sync(0xffffffffu, tm1, 1));
        tm1 = fmaxf(tm1, __shfl_xor_sync(0xffffffffu, tm1, 2));
        float nm0 = fmaxf(m0r, tm0), nm1 = fmaxf(m1r, tm1);
        float sc0 = __expf(m0r - nm0), sc1 = __expf(m1r - nm1);
        m0r = nm0; m1r = nm1;
        l0 *= sc0; l1 *= sc1;
#pragma unroll
        for (int nt = 0; nt < 8; nt++){
            s[nt][0] = __expf(s[nt][0] - nm0);
            s[nt][1] = __expf(s[nt][1] - nm0);
            s[nt][2] = __expf(s[nt][2] - nm1);
            s[nt][3] = __expf(s[nt][3] - nm1);
            l0 += s[nt][0] + s[nt][1];
            l1 += s[nt][2] + s[nt][3];
        }
        uint32_t pa[4][4], pb[4][4];
#pragma unroll
        for (int kt = 0; kt < 4; kt++){
            hsplit2(s[2*kt][0],   s[2*kt][1],   pa[kt][0], pb[kt][0]);
            hsplit2(s[2*kt][2],   s[2*kt][3],   pa[kt][1], pb[kt][1]);
            hsplit2(s[2*kt+1][0], s[2*kt+1][1], pa[kt][2], pb[kt][2]);
            hsplit2(s[2*kt+1][2], s[2*kt+1][3], pa[kt][3], pb[kt][3]);
        }
#pragma unroll
        for (int nt = 0; nt < NO; nt++){
            o[nt][0] *= sc0; o[nt][1] *= sc0; o[nt][2] *= sc1; o[nt][3] *= sc1;
        }
        const int rV = (lane & 7) + ((lane & 8) ? 8 : 0);
        const int cV8 = (lane >> 4) * 8;
#pragma unroll
        for (int nt = 0; nt < NO; nt += 2){
#pragma unroll
            for (int kt = 0; kt < 4; kt++){
                uint32_t va0, va1, va2, va3, vb0, vb1, vb2, vb3;
                ldsm4t(va0, va1, va2, va3, kbase + (kt*16 + rV)*LDRB + (nt*8 + cV8)*2);
                ldsm4t(vb0, vb1, vb2, vb3, kbase + KLIMB + (kt*16 + rV)*LDRB + (nt*8 + cV8)*2);
                mma16816(o[nt],   pa[kt], va0, va1);
                mma16816(o[nt],   pa[kt], vb0, vb1);
                mma16816(o[nt],   pb[kt], va0, va1);
                mma16816(o[nt+1], pa[kt], va2, va3);
                mma16816(o[nt+1], pa[kt], vb2, vb3);
                mma16816(o[nt+1], pb[kt], va2, va3);
            }
        }
        __syncthreads();
    }

    // epilogue
    l0 += __shfl_xor_sync(0xffffffffu, l0, 1);
    l0 += __shfl_xor_sync(0xffffffffu, l0, 2);
    l1 += __shfl_xor_sync(0xffffffffu, l1, 1);
    l1 += __shfl_xor_sync(0xffffffffu, l1, 2);
    float li0 = 1.f / l0, li1 = 1.f / l1;
    if (LAYER == 1){
        const float* bias = bias_g + h*HID_;
        const size_t i0 = ((size_t)b*N_ + row0)*CAT_ + h*HID_;
        const size_t i1 = ((size_t)b*N_ + row0 + 8)*CAT_ + h*HID_;
#pragma unroll
        for (int nt = 0; nt < NO; nt++){
            int c = nt*8 + 2*q4;
            float b0 = bias[c], b1 = bias[c+1];
            float v0 = fmaf(o[nt][0], li0, b0), v1 = fmaf(o[nt][1], li0, b1);
            float v2 = fmaf(o[nt][2], li1, b0), v3 = fmaf(o[nt][3], li1, b1);
            v0 = (v0 > 0.f) ? v0 : 0.01f*v0; v1 = (v1 > 0.f) ? v1 : 0.01f*v1;
            v2 = (v2 > 0.f) ? v2 : 0.01f*v2; v3 = (v3 > 0.f) ? v3 : 0.01f*v3;
            uint32_t ua, ub;
            hsplit2(v0, v1, ua, ub);
            *(uint32_t*)(g_ca + i0 + c) = ua;
            *(uint32_t*)(g_cb + i0 + c) = ub;
            hsplit2(v2, v3, ua, ub);
            *(uint32_t*)(g_ca + i1 + c) = ua;
            *(uint32_t*)(g_cb + i1 + c) = ub;
        }
    } else {
        const float* bias = bias_g;
        float* d0 = out2 + ((size_t)b*N_ + row0)*COUT_;
        float* d1 = out2 + ((size_t)b*N_ + row0 + 8)*COUT_;
#pragma unroll
        for (int nt = 0; nt < NO; nt++){
            int c = nt*8 + 2*q4;
            float b0 = bias[c], b1 = bias[c+1];
            float v0 = fmaf(o[nt][0], li0, b0), v1 = fmaf(o[nt][1], li0, b1);
            float v2 = fmaf(o[nt][2], li1, b0), v3 = fmaf(o[nt][3], li1, b1);
            v0 = (v0 > 0.f) ? v0 : 0.01f*v0; v1 = (v1 > 0.f) ? v1 : 0.01f*v1;
            v2 = (v2 > 0.f) ? v2 : 0.01f*v2; v3 = (v3 > 0.f) ? v3 : 0.01f*v3;
            *(float2*)(d0 + c) = make_float2(v0, v1);
            *(float2*)(d1 + c) = make_float2(v2, v3);
        }
    }
}

// ---------------------------------------------------------------------------
// gemm2 via HMMA: g_ha/g_hb = (g_ca,g_cb) @ (g_wa,g_wb), 3-product limb emu.
// ---------------------------------------------------------------------------
constexpr int G2_LDR = (64 + 8) * 2;            // 144 B rows
constexpr int G2_A = 64 * G2_LDR;
constexpr int G2_CHUNK = 4*G2_A;
__global__ __launch_bounds__(128, 1) void gemm2_mma(){
    extern __shared__ char sm[];
    const uint32_t sb = smem_u32(sm);
    const int tid = threadIdx.x, w = tid >> 5, lane = tid & 31;
    const int bn0 = blockIdx.x * 64;

    float o[8][4];
#pragma unroll
    for (int i = 0; i < 8; i++){ o[i][0]=0.f; o[i][1]=0.f; o[i][2]=0.f; o[i][3]=0.f; }

    for (int i = tid; i < 64*8; i += 128){
        int r = i >> 3, ch = i & 7;
        cpa16(sb + 0*G2_A + r*G2_LDR + ch*16, g_ca + (size_t)(bn0+r)*CAT_ + ch*8);
        cpa16(sb + 1*G2_A + r*G2_LDR + ch*16, g_cb + (size_t)(bn0+r)*CAT_ + ch*8);
        cpa16(sb + 2*G2_A + r*G2_LDR + ch*16, g_wa + (size_t)r*COUT_ + ch*8);
        cpa16(sb + 3*G2_A + r*G2_LDR + ch*16, g_wb + (size_t)r*COUT_ + ch*8);
    }
    CPA_COMMIT();

    for (int t = 0; t < 16; t++){
        const uint32_t base = sb + (t & 1)*G2_CHUNK;
        if (t < 15){
            const int k1 = (t+1)*64;
            const uint32_t nb = sb + ((t+1) & 1)*G2_CHUNK;
            for (int i = tid; i < 64*8; i += 128){
                int r = i >> 3, ch = i & 7;
                cpa16(nb + 0*G2_A + r*G2_LDR + ch*16, g_ca + (size_t)(bn0+r)*CAT_ + k1 + ch*8);
                cpa16(nb + 1*G2_A + r*G2_LDR + ch*16, g_cb + (size_t)(bn0+r)*CAT_ + k1 + ch*8);
                cpa16(nb + 2*G2_A + r*G2_LDR + ch*16, g_wa + (size_t)(k1+r)*COUT_ + ch*8);
                cpa16(nb + 3*G2_A + r*G2_LDR + ch*16, g_wb + (size_t)(k1+r)*COUT_ + ch*8);
            }
            CPA_COMMIT();
            CPA_WAIT(1);
        } else {
            CPA_WAIT(0);
        }
        __syncthreads();

        uint32_t aa[4][4], ab[4][4];
        const int rowA = w*16 + (lane & 15);
        const int colA = (lane >> 4) * 8;
#pragma unroll
        for (int kt = 0; kt < 4; kt++){
            ldsm4(aa[kt][0], aa[kt][1], aa[kt][2], aa[kt][3], base + 0*G2_A + rowA*G2_LDR + (kt*16 + colA)*2);
            ldsm4(ab[kt][0], ab[kt][1], ab[kt][2], ab[kt][3], base + 1*G2_A + rowA*G2_LDR + (kt*16 + colA)*2);
        }
        const int rV = (lane & 7) + ((lane & 8) ? 8 : 0);
        const int cV8 = (lane >> 4) * 8;
#pragma unroll
        for (int ng = 0; ng < 4; ng++){
#pragma unroll
            for (int kt = 0; kt < 4; kt++){
                uint32_t wa0, wa1, wa2, wa3, wb0, wb1, wb2, wb3;
                ldsm4t(wa0, wa1, wa2, wa3, base + 2*G2_A + (kt*16 + rV)*G2_LDR + (ng*16 + cV8)*2);
                ldsm4t(wb0, wb1, wb2, wb3, base + 3*G2_A + (kt*16 + rV)*G2_LDR + (ng*16 + cV8)*2);
                mma16816(o[ng*2],   aa[kt], wa0, wa1);
                mma16816(o[ng*2],   aa[kt], wb0, wb1);
                mma16816(o[ng*2],   ab[kt], wa0, wa1);
                mma16816(o[ng*2+1], aa[kt], wa2, wa3);
                mma16816(o[ng*2+1], aa[kt], wb2, wb3);
                mma16816(o[ng*2+1], ab[kt], wa2, wa3);
            }
        }
        __syncthreads();
    }

    const int g = lane >> 2, q4 = lane & 3;
    const size_t r0 = (size_t)(bn0 + w*16 + g)*COUT_;
    const size_t r1 = (size_t)(bn0 + w*16 + g + 8)*COUT_;
#pragma unroll
    for (int nt = 0; nt < 8; nt++){
        int c = nt*8 + 2*q4;
        uint32_t ua, ub;
        hsplit2(o[nt][0], o[nt][1], ua, ub);
        *(uint32_t*)(g_ha + r0 + c) = ua;
        *(uint32_t*)(g_hb + r0 + c) = ub;
        hsplit2(o[nt][2], o[nt][3], ua, ub);
        *(uint32_t*)(g_ha + r1 + c) = ua;
        *(uint32_t*)(g_hb + r1 + c) = ub;
    }
}

extern "C" void kernel_launch(void* const* d_in, const int* in_sizes, int n_in,
                              void* d_out, int out_size){
    const float* flow_x = (const float*)d_in[0];
    const float* graph  = (const float*)d_in[1];
    const float* Wh     = (const float*)d_in[2];
    const float* bh     = (const float*)d_in[3];
    const float* W_out  = (const float*)d_in[4];
    const float* b_out  = (const float*)d_in[5];
    float* out = (float*)d_out;

    // attn1 at QROWS=64: smem = 2*64*272 + 2*2*64*272 = 104448 -> 2 CTAs/SM
    constexpr int SM1 = 2*64*(128+8)*2 + 2*2*64*(128+8)*2;   // 104448
    constexpr int SM2 = 2*64*(64+8)*2  + 2*2*64*(64+8)*2;    // 55296
    constexpr int SMG2 = 2*G2_CHUNK;                         // 73728
    cudaFuncSetAttribute(attn_mma<128,1,64>, cudaFuncAttributeMaxDynamicSharedMemorySize, SM1);
    cudaFuncSetAttribute(attn_mma<64,2,64>,  cudaFuncAttributeMaxDynamicSharedMemorySize, SM2);
    cudaFuncSetAttribute(gemm2_mma,          cudaFuncAttributeMaxDynamicSharedMemorySize, SMG2);

    gemm1_kernel<<<dim3(B_*N_/64, H_), 256>>>(flow_x, Wh);
    graph_bits_kernel<<<128, 256>>>(graph);
    wsplit_kernel<<<128, 256>>>(W_out);
    attn_mma<128,1,64><<<dim3(N_/64, B_, H_), 128, SM1>>>(bh, nullptr);
    gemm2_mma<<<dim3(B_*N_/64), 128, SMG2>>>();
    attn_mma<64,2,64><<<dim3(N_/64, B_, 1), 128, SM2>>>(b_out, out);
}

// round 17
// speedup vs baseline: 1.5089x; 1.5089x over previous
#include <cuda_runtime.h>
#include <cuda_fp16.h>
#include <math.h>
#include <stdint.h>

constexpr int B_=16, N_=1024, CIN_=64, HID_=128, H_=8, COUT_=64, CAT_=HID_*H_;
typedef unsigned long long ull;

// device scratch (no allocation allowed)
__device__ __half g_ka[(size_t)B_*H_*N_*HID_];   // L1 feature limb hi, [bh][n][d]
__device__ __half g_kb[(size_t)B_*H_*N_*HID_];   // L1 feature limb lo
__device__ __half g_ca[(size_t)B_*N_*CAT_];      // L1 activated output limb hi
__device__ __half g_cb[(size_t)B_*N_*CAT_];      // L1 activated output limb lo
__device__ __half g_wa[CAT_*COUT_];              // W_out limb hi [k][n]
__device__ __half g_wb[CAT_*COUT_];              // W_out limb lo
__device__ __half g_ha[(size_t)B_*N_*COUT_];     // L2 feature limb hi
__device__ __half g_hb[(size_t)B_*N_*COUT_];     // L2 feature limb lo
__device__ uint32_t g_bits[N_*(N_/32)];          // adjacency bitmask

// ---- f32x2 helpers ----
__device__ __forceinline__ ull f2pack(float lo, float hi){ ull r; asm("mov.b64 %0, {%1, %2};" : "=l"(r) : "f"(lo), "f"(hi)); return r; }
__device__ __forceinline__ float2 f2unpack(ull v){ float2 r; asm("mov.b64 {%0, %1}, %2;" : "=f"(r.x), "=f"(r.y) : "l"(v)); return r; }
__device__ __forceinline__ ull ffma2(ull a, ull b, ull c){ ull d; asm("fma.rn.f32x2 %0, %1, %2, %3;" : "=l"(d) : "l"(a), "l"(b), "l"(c)); return d; }

__device__ __forceinline__ uint32_t smem_u32(const void* p){ uint32_t a; asm("{ .reg .u64 t; cvta.to.shared.u64 t, %1; cvt.u32.u64 %0, t; }" : "=r"(a) : "l"(p)); return a; }

// ---- baseline-PTX tensor + async ops (compute_103-safe) ----
__device__ __forceinline__ void ldsm4(uint32_t& r0, uint32_t& r1, uint32_t& r2, uint32_t& r3, uint32_t addr){
    asm volatile("ldmatrix.sync.aligned.m8n8.x4.shared.b16 {%0,%1,%2,%3}, [%4];"
        : "=r"(r0), "=r"(r1), "=r"(r2), "=r"(r3) : "r"(addr));
}
__device__ __forceinline__ void ldsm4t(uint32_t& r0, uint32_t& r1, uint32_t& r2, uint32_t& r3, uint32_t addr){
    asm volatile("ldmatrix.sync.aligned.m8n8.x4.trans.shared.b16 {%0,%1,%2,%3}, [%4];"
        : "=r"(r0), "=r"(r1), "=r"(r2), "=r"(r3) : "r"(addr));
}
__device__ __forceinline__ void mma16816(float* c, const uint32_t* a, uint32_t b0, uint32_t b1){
    asm volatile("mma.sync.aligned.m16n8k16.row.col.f32.f16.f16.f32 "
        "{%0,%1,%2,%3}, {%4,%5,%6,%7}, {%8,%9}, {%0,%1,%2,%3};"
        : "+f"(c[0]), "+f"(c[1]), "+f"(c[2]), "+f"(c[3])
        : "r"(a[0]), "r"(a[1]), "r"(a[2]), "r"(a[3]), "r"(b0), "r"(b1));
}
// fast 2-limb split using packed converts (identical rounding to scalar version)
__device__ __forceinline__ void hsplit2(float x, float y, uint32_t& a, uint32_t& b){
    __half2 hi = __floats2half2_rn(x, y);
    float2 f = __half22float2(hi);
    __half2 lo = __floats2half2_rn(x - f.x, y - f.y);
    a = *reinterpret_cast<uint32_t*>(&hi);
    b = *reinterpret_cast<uint32_t*>(&lo);
}
__device__ __forceinline__ void cpa16(uint32_t saddr, const void* g){
    asm volatile("cp.async.cg.shared.global [%0], [%1], 16;" :: "r"(saddr), "l"(g));
}
#define CPA_COMMIT() asm volatile("cp.async.commit_group;" ::: "memory")
#define CPA_WAIT(n)  asm volatile("cp.async.wait_group %0;" :: "n"(n) : "memory")

// graph -> bitmask
__global__ __launch_bounds__(256) void graph_bits_kernel(const float* __restrict__ graph){
    int w = blockIdx.x*256 + threadIdx.x;
    int row = w >> 5, c0 = (w & 31) * 32;
    uint32_t bits = 0;
#pragma unroll 8
    for (int j = 0; j < 32; j++)
        bits |= (graph[(size_t)row*N_ + c0 + j] != 0.f ? 1u : 0u) << j;
    g_bits[w] = bits;
}

// W_out -> fp16 limbs
__global__ __launch_bounds__(256) void wsplit_kernel(const float* __restrict__ Wout){
    int i = blockIdx.x*256 + threadIdx.x;
    float2 v = *(const float2*)(Wout + i*2);
    uint32_t a, b;
    hsplit2(v.x, v.y, a, b);
    *(uint32_t*)(g_wa + i*2) = a;
    *(uint32_t*)(g_wb + i*2) = b;
}

// gemm1: per-head GEMM, epilogue splits features into fp16 2-limb arrays [bh][n][d]
__global__ __launch_bounds__(256) void gemm1_kernel(const float* __restrict__ x,
                                                    const float* __restrict__ Wh){
    __shared__ float sX[64*CIN_];
    __shared__ float sW[CIN_*HID_];
    const int tid = threadIdx.x, tx = tid & 15, ty = tid >> 4;
    const int bn0 = blockIdx.x * 64, h = blockIdx.y;
    const float* Wp = Wh + (size_t)h*CIN_*HID_;

    for (int i = tid; i < CIN_*HID_/4; i += 256)
        *(float4*)(sW + i*4) = *(const float4*)(Wp + i*4);
    for (int i = tid; i < 64*CIN_/4; i += 256){
        int r = i >> 4, c4 = i & 15;
        *(float4*)(sX + r*CIN_ + c4*4) = *(const float4*)(x + (size_t)(bn0+r)*CIN_ + c4*4);
    }
    __syncthreads();

    ull a2[4][4];
#pragma unroll
    for (int i = 0; i < 4; i++)
#pragma unroll
        for (int j = 0; j < 4; j++) a2[i][j] = 0ull;
#pragma unroll 4
    for (int k4 = 0; k4 < CIN_; k4 += 4){
        float4 av[4];
#pragma unroll
        for (int i = 0; i < 4; i++) av[i] = *(const float4*)(sX + (ty*4+i)*CIN_ + k4);
#pragma unroll
        for (int k = 0; k < 4; k++){
            ulonglong2 wv[2];
#pragma unroll
            for (int g = 0; g < 2; g++) wv[g] = *(const ulonglong2*)(sW + (k4+k)*HID_ + 64*g + 4*tx);
#pragma unroll
            for (int i = 0; i < 4; i++){
                float a = ((const float*)&av[i])[k];
                ull pp = f2pack(a, a);
#pragma unroll
                for (int g = 0; g < 2; g++){
                    a2[i][g*2+0] = ffma2(pp, wv[g].x, a2[i][g*2+0]);
                    a2[i][g*2+1] = ffma2(pp, wv[g].y, a2[i][g*2+1]);
                }
            }
        }
    }
#pragma unroll
    for (int i = 0; i < 4; i++){
        const int bn = bn0 + ty*4 + i, bb = bn >> 10, nn = bn & 1023;
        const size_t base = ((size_t)(bb*H_+h)*N_ + nn)*HID_;
#pragma unroll
        for (int g = 0; g < 2; g++){
            float2 e0 = f2unpack(a2[i][g*2+0]), e1 = f2unpack(a2[i][g*2+1]);
            uint32_t pa0, pb0, pa1, pb1;
            hsplit2(e0.x, e0.y, pa0, pb0);
            hsplit2(e1.x, e1.y, pa1, pb1);
            size_t ki = base + 64*g + 4*tx;
            *(uint2*)(g_ka + ki) = make_uint2(pa0, pa1);
            *(uint2*)(g_kb + ki) = make_uint2(pb0, pb1);
        }
    }
}

// ---------------------------------------------------------------------------
// Unified fp16 2-limb emulated-fp32 flash attention via mma.sync.
// QROWS q-rows per CTA, QROWS/16 warps. kv tiles of 64, cp.async double-buffer.
// ---------------------------------------------------------------------------
template <int D, int LAYER, int QROWS>
__global__ __launch_bounds__(QROWS*2, 1) void attn_mma(const float* __restrict__ bias_g,
                                                       float* __restrict__ out2){
    constexpr int THREADS = QROWS*2;
    constexpr int KT = D / 16;
    constexpr int NO = D / 8;
    constexpr int CH = D / 8;
    constexpr int LDRB = (D + 8) * 2;
    constexpr int QLIMB = QROWS * LDRB;
    constexpr int KLIMB = 64 * LDRB;
    constexpr int KBUF = 2 * KLIMB;
    constexpr int OFF_K = 2 * QLIMB;

    extern __shared__ char sm[];
    const uint32_t sb = smem_u32(sm);
    const int tid = threadIdx.x, w = tid >> 5, lane = tid & 31;
    const int n0q = blockIdx.x * QROWS, b = blockIdx.y, h = blockIdx.z;
    const __half* Fa;
    const __half* Fb;
    if (LAYER == 1){
        const size_t bhoff = (size_t)(b*H_ + h);
        Fa = g_ka + bhoff*N_*HID_;
        Fb = g_kb + bhoff*N_*HID_;
    } else {
        Fa = g_ha + (size_t)b*N_*COUT_;
        Fb = g_hb + (size_t)b*N_*COUT_;
    }

    // stage Q
    for (int i = tid; i < QROWS*CH; i += THREADS){
        int r = i / CH, ch = i % CH;
        *(uint4*)(sm + 0     + r*LDRB + ch*16) = *(const uint4*)(Fa + (size_t)(n0q+r)*D + ch*8);
        *(uint4*)(sm + QLIMB + r*LDRB + ch*16) = *(const uint4*)(Fb + (size_t)(n0q+r)*D + ch*8);
    }
    __syncthreads();

    uint32_t qa[KT][4], qb[KT][4];
    {
        const int rowA = w*16 + (lane & 15);
        const int colA = (lane >> 4) * 8;
#pragma unroll
        for (int kt = 0; kt < KT; kt++){
            ldsm4(qa[kt][0], qa[kt][1], qa[kt][2], qa[kt][3], sb + 0     + rowA*LDRB + (kt*16 + colA)*2);
            ldsm4(qb[kt][0], qb[kt][1], qb[kt][2], qb[kt][3], sb + QLIMB + rowA*LDRB + (kt*16 + colA)*2);
        }
    }

    float o[NO][4];
#pragma unroll
    for (int i = 0; i < NO; i++){ o[i][0]=0.f; o[i][1]=0.f; o[i][2]=0.f; o[i][3]=0.f; }
    float m0r = -INFINITY, m1r = -INFINITY, l0 = 0.f, l1 = 0.f;

    const int g = lane >> 2, q4 = lane & 3;
    const int row0 = n0q + w*16 + g;

    for (int i = tid; i < 64*CH; i += THREADS){
        int r = i / CH, ch = i % CH;
        cpa16(sb + OFF_K + r*LDRB + ch*16,         Fa + (size_t)r*D + ch*8);
        cpa16(sb + OFF_K + KLIMB + r*LDRB + ch*16, Fb + (size_t)r*D + ch*8);
    }
    CPA_COMMIT();

    for (int t = 0; t < 16; t++){
        const uint32_t kbase = sb + OFF_K + (t & 1)*KBUF;
        if (t < 15){
            const int m1 = (t+1)*64;
            const uint32_t nb = sb + OFF_K + ((t+1) & 1)*KBUF;
            for (int i = tid; i < 64*CH; i += THREADS){
                int r = i / CH, ch = i % CH;
                cpa16(nb + r*LDRB + ch*16,         Fa + (size_t)(m1+r)*D + ch*8);
                cpa16(nb + KLIMB + r*LDRB + ch*16, Fb + (size_t)(m1+r)*D + ch*8);
            }
            CPA_COMMIT();
            CPA_WAIT(1);
        } else {
            CPA_WAIT(0);
        }
        __syncthreads();

        uint2 gb0 = *(const uint2*)&g_bits[(size_t)row0*32 + t*2];
        uint2 gb1 = *(const uint2*)&g_bits[(size_t)(row0+8)*32 + t*2];

        float s[8][4];
#pragma unroll
        for (int nt = 0; nt < 8; nt++){ s[nt][0]=0.f; s[nt][1]=0.f; s[nt][2]=0.f; s[nt][3]=0.f; }
        const int rowB = (lane & 7);
        const int colB8 = (lane >> 3) * 8;
#pragma unroll
        for (int nt = 0; nt < 8; nt++){
#pragma unroll
            for (int ktp = 0; ktp < KT/2; ktp++){
                uint32_t ka0, ka1, ka2, ka3, kb0, kb1, kb2, kb3;
                ldsm4(ka0, ka1, ka2, ka3, kbase + (nt*8 + rowB)*LDRB + (ktp*32 + colB8)*2);
                ldsm4(kb0, kb1, kb2, kb3, kbase + KLIMB + (nt*8 + rowB)*LDRB + (ktp*32 + colB8)*2);
                const int kt = 2*ktp;
                mma16816(s[nt], qa[kt],   ka0, ka1);
                mma16816(s[nt], qa[kt],   kb0, kb1);
                mma16816(s[nt], qb[kt],   ka0, ka1);
                mma16816(s[nt], qa[kt+1], ka2, ka3);
                mma16816(s[nt], qa[kt+1], kb2, kb3);
                mma16816(s[nt], qb[kt+1], ka2, ka3);
            }
        }

        float tm0 = -INFINITY, tm1 = -INFINITY;
#pragma unroll
        for (int nt = 0; nt < 8; nt++){
            int c0 = nt*8 + 2*q4, c1 = c0 + 1;
            uint32_t w00 = (c0 < 32) ? gb0.x : gb0.y;
            uint32_t w10 = (c0 < 32) ? gb1.x : gb1.y;
            if (!((w00 >> (c0 & 31)) & 1u)) s[nt][0] = -1e16f;
            if (!((w00 >> (c1 & 31)) & 1u)) s[nt][1] = -1e16f;
            if (!((w10 >> (c0 & 31)) & 1u)) s[nt][2] = -1e16f;
            if (!((w10 >> (c1 & 31)) & 1u)) s[nt][3] = -1e16f;
            tm0 = fmaxf(tm0, fmaxf(s[nt][0], s[nt][1]));
            tm1 = fmaxf(tm1, fmaxf(s[nt][2], s[nt][3]));
        }
        tm0 = fmaxf(tm0, __shfl_xor_sync(0xffffffffu, tm0, 1));
        tm0 = fmaxf(tm0, __shfl_xor_sync(0xffffffffu, tm0, 2));
        tm1 = fmaxf(tm1, __shfl_xor_sync(0xffffffffu, tm1, 1));
        tm1 = fmaxf(tm1, __shfl_xor_sync(0xffffffffu, tm1, 2));
        float nm0 = fmaxf(m0r, tm0), nm1 = fmaxf(m1r, tm1);
        float sc0 = __expf(m0r - nm0), sc1 = __expf(m1r - nm1);
        m0r = nm0; m1r = nm1;
        l0 *= sc0; l1 *= sc1;
#pragma unroll
        for (int nt = 0; nt < 8; nt++){
            s[nt][0] = __expf(s[nt][0] - nm0);
            s[nt][1] = __expf(s[nt][1] - nm0);
            s[nt][2] = __expf(s[nt][2] - nm1);
            s[nt][3] = __expf(s[nt][3] - nm1);
            l0 += s[nt][0] + s[nt][1];
            l1 += s[nt][2] + s[nt][3];
        }
        uint32_t pa[4][4], pb[4][4];
#pragma unroll
        for (int kt = 0; kt < 4; kt++){
            hsplit2(s[2*kt][0],   s[2*kt][1],   pa[kt][0], pb[kt][0]);
            hsplit2(s[2*kt][2],   s[2*kt][3],   pa[kt][1], pb[kt][1]);
            hsplit2(s[2*kt+1][0], s[2*kt+1][1], pa[kt][2], pb[kt][2]);
            hsplit2(s[2*kt+1][2], s[2*kt+1][3], pa[kt][3], pb[kt][3]);
        }
        // conditional O-rescale: exact skip when no row max changed in this warp
        if (__any_sync(0xffffffffu, (sc0 < 1.f) | (sc1 < 1.f))){
#pragma unroll
            for (int nt = 0; nt < NO; nt++){
                o[nt][0] *= sc0; o[nt][1] *= sc0; o[nt][2] *= sc1; o[nt][3] *= sc1;
            }
        }
        const int rV = (lane & 7) + ((lane & 8) ? 8 : 0);
        const int cV8 = (lane >> 4) * 8;
#pragma unroll
        for (int nt = 0; nt < NO; nt += 2){
#pragma unroll
            for (int kt = 0; kt < 4; kt++){
                uint32_t va0, va1, va2, va3, vb0, vb1, vb2, vb3;
                ldsm4t(va0, va1, va2, va3, kbase + (kt*16 + rV)*LDRB + (nt*8 + cV8)*2);
                ldsm4t(vb0, vb1, vb2, vb3, kbase + KLIMB + (kt*16 + rV)*LDRB + (nt*8 + cV8)*2);
                mma16816(o[nt],   pa[kt], va0, va1);
                mma16816(o[nt],   pa[kt], vb0, vb1);
                mma16816(o[nt],   pb[kt], va0, va1);
                mma16816(o[nt+1], pa[kt], va2, va3);
                mma16816(o[nt+1], pa[kt], vb2, vb3);
                mma16816(o[nt+1], pb[kt], va2, va3);
            }
        }
        __syncthreads();
    }

    // epilogue
    l0 += __shfl_xor_sync(0xffffffffu, l0, 1);
    l0 += __shfl_xor_sync(0xffffffffu, l0, 2);
    l1 += __shfl_xor_sync(0xffffffffu, l1, 1);
    l1 += __shfl_xor_sync(0xffffffffu, l1, 2);
    float li0 = 1.f / l0, li1 = 1.f / l1;
    if (LAYER == 1){
        const float* bias = bias_g + h*HID_;
        const size_t i0 = ((size_t)b*N_ + row0)*CAT_ + h*HID_;
        const size_t i1 = ((size_t)b*N_ + row0 + 8)*CAT_ + h*HID_;
#pragma unroll
        for (int nt = 0; nt < NO; nt++){
            int c = nt*8 + 2*q4;
            float b0 = bias[c], b1 = bias[c+1];
            float v0 = fmaf(o[nt][0], li0, b0), v1 = fmaf(o[nt][1], li0, b1);
            float v2 = fmaf(o[nt][2], li1, b0), v3 = fmaf(o[nt][3], li1, b1);
            v0 = (v0 > 0.f) ? v0 : 0.01f*v0; v1 = (v1 > 0.f) ? v1 : 0.01f*v1;
            v2 = (v2 > 0.f) ? v2 : 0.01f*v2; v3 = (v3 > 0.f) ? v3 : 0.01f*v3;
            uint32_t ua, ub;
            hsplit2(v0, v1, ua, ub);
            *(uint32_t*)(g_ca + i0 + c) = ua;
            *(uint32_t*)(g_cb + i0 + c) = ub;
            hsplit2(v2, v3, ua, ub);
            *(uint32_t*)(g_ca + i1 + c) = ua;
            *(uint32_t*)(g_cb + i1 + c) = ub;
        }
    } else {
        const float* bias = bias_g;
        float* d0 = out2 + ((size_t)b*N_ + row0)*COUT_;
        float* d1 = out2 + ((size_t)b*N_ + row0 + 8)*COUT_;
#pragma unroll
        for (int nt = 0; nt < NO; nt++){
            int c = nt*8 + 2*q4;
            float b0 = bias[c], b1 = bias[c+1];
            float v0 = fmaf(o[nt][0], li0, b0), v1 = fmaf(o[nt][1], li0, b1);
            float v2 = fmaf(o[nt][2], li1, b0), v3 = fmaf(o[nt][3], li1, b1);
            v0 = (v0 > 0.f) ? v0 : 0.01f*v0; v1 = (v1 > 0.f) ? v1 : 0.01f*v1;
            v2 = (v2 > 0.f) ? v2 : 0.01f*v2; v3 = (v3 > 0.f) ? v3 : 0.01f*v3;
            *(float2*)(d0 + c) = make_float2(v0, v1);
            *(float2*)(d1 + c) = make_float2(v2, v3);
        }
    }
}

// ---------------------------------------------------------------------------
// gemm2 via HMMA: g_ha/g_hb = (g_ca,g_cb) @ (g_wa,g_wb), 3-product limb emu.
// ---------------------------------------------------------------------------
constexpr int G2_LDR = (64 + 8) * 2;            // 144 B rows
constexpr int G2_A = 64 * G2_LDR;
constexpr int G2_CHUNK = 4*G2_A;
__global__ __launch_bounds__(128, 1) void gemm2_mma(){
    extern __shared__ char sm[];
    const uint32_t sb = smem_u32(sm);
    const int tid = threadIdx.x, w = tid >> 5, lane = tid & 31;
    const int bn0 = blockIdx.x * 64;

    float o[8][4];
#pragma unroll
    for (int i = 0; i < 8; i++){ o[i][0]=0.f; o[i][1]=0.f; o[i][2]=0.f; o[i][3]=0.f; }

    for (int i = tid; i < 64*8; i += 128){
        int r = i >> 3, ch = i & 7;
        cpa16(sb + 0*G2_A + r*G2_LDR + ch*16, g_ca + (size_t)(bn0+r)*CAT_ + ch*8);
        cpa16(sb + 1*G2_A + r*G2_LDR + ch*16, g_cb + (size_t)(bn0+r)*CAT_ + ch*8);
        cpa16(sb + 2*G2_A + r*G2_LDR + ch*16, g_wa + (size_t)r*COUT_ + ch*8);
        cpa16(sb + 3*G2_A + r*G2_LDR + ch*16, g_wb + (size_t)r*COUT_ + ch*8);
    }
    CPA_COMMIT();

    for (int t = 0; t < 16; t++){
        const uint32_t base = sb + (t & 1)*G2_CHUNK;
        if (t < 15){
            const int k1 = (t+1)*64;
            const uint32_t nb = sb + ((t+1) & 1)*G2_CHUNK;
            for (int i = tid; i < 64*8; i += 128){
                int r = i >> 3, ch = i & 7;
                cpa16(nb + 0*G2_A + r*G2_LDR + ch*16, g_ca + (size_t)(bn0+r)*CAT_ + k1 + ch*8);
                cpa16(nb + 1*G2_A + r*G2_LDR + ch*16, g_cb + (size_t)(bn0+r)*CAT_ + k1 + ch*8);
                cpa16(nb + 2*G2_A + r*G2_LDR + ch*16, g_wa + (size_t)(k1+r)*COUT_ + ch*8);
                cpa16(nb + 3*G2_A + r*G2_LDR + ch*16, g_wb + (size_t)(k1+r)*COUT_ + ch*8);
            }
            CPA_COMMIT();
            CPA_WAIT(1);
        } else {
            CPA_WAIT(0);
        }
        __syncthreads();

        uint32_t aa[4][4], ab[4][4];
        const int rowA = w*16 + (lane & 15);
        const int colA = (lane >> 4) * 8;
#pragma unroll
        for (int kt = 0; kt < 4; kt++){
            ldsm4(aa[kt][0], aa[kt][1], aa[kt][2], aa[kt][3], base + 0*G2_A + rowA*G2_LDR + (kt*16 + colA)*2);
            ldsm4(ab[kt][0], ab[kt][1], ab[kt][2], ab[kt][3], base + 1*G2_A + rowA*G2_LDR + (kt*16 + colA)*2);
        }
        const int rV = (lane & 7) + ((lane & 8) ? 8 : 0);
        const int cV8 = (lane >> 4) * 8;
#pragma unroll
        for (int ng = 0; ng < 4; ng++){
#pragma unroll
            for (int kt = 0; kt < 4; kt++){
                uint32_t wa0, wa1, wa2, wa3, wb0, wb1, wb2, wb3;
                ldsm4t(wa0, wa1, wa2, wa3, base + 2*G2_A + (kt*16 + rV)*G2_LDR + (ng*16 + cV8)*2);
                ldsm4t(wb0, wb1, wb2, wb3, base + 3*G2_A + (kt*16 + rV)*G2_LDR + (ng*16 + cV8)*2);
                mma16816(o[ng*2],   aa[kt], wa0, wa1);
                mma16816(o[ng*2],   aa[kt], wb0, wb1);
                mma16816(o[ng*2],   ab[kt], wa0, wa1);
                mma16816(o[ng*2+1], aa[kt], wa2, wa3);
                mma16816(o[ng*2+1], aa[kt], wb2, wb3);
                mma16816(o[ng*2+1], ab[kt], wa2, wa3);
            }
        }
        __syncthreads();
    }

    const int g = lane >> 2, q4 = lane & 3;
    const size_t r0 = (size_t)(bn0 + w*16 + g)*COUT_;
    const size_t r1 = (size_t)(bn0 + w*16 + g + 8)*COUT_;
#pragma unroll
    for (int nt = 0; nt < 8; nt++){
        int c = nt*8 + 2*q4;
        uint32_t ua, ub;
        hsplit2(o[nt][0], o[nt][1], ua, ub);
        *(uint32_t*)(g_ha + r0 + c) = ua;
        *(uint32_t*)(g_hb + r0 + c) = ub;
        hsplit2(o[nt][2], o[nt][3], ua, ub);
        *(uint32_t*)(g_ha + r1 + c) = ua;
        *(uint32_t*)(g_hb + r1 + c) = ub;
    }
}

extern "C" void kernel_launch(void* const* d_in, const int* in_sizes, int n_in,
                              void* d_out, int out_size){
    const float* flow_x = (const float*)d_in[0];
    const float* graph  = (const float*)d_in[1];
    const float* Wh     = (const float*)d_in[2];
    const float* bh     = (const float*)d_in[3];
    const float* W_out  = (const float*)d_in[4];
    const float* b_out  = (const float*)d_in[5];
    float* out = (float*)d_out;

    constexpr int SM1 = 2*128*(128+8)*2 + 2*2*64*(128+8)*2;  // 139264
    constexpr int SM2 = 2*64*(64+8)*2  + 2*2*64*(64+8)*2;    // 55296
    constexpr int SMG2 = 2*G2_CHUNK;                         // 73728
    cudaFuncSetAttribute(attn_mma<128,1,128>, cudaFuncAttributeMaxDynamicSharedMemorySize, SM1);
    cudaFuncSetAttribute(attn_mma<64,2,64>,   cudaFuncAttributeMaxDynamicSharedMemorySize, SM2);
    cudaFuncSetAttribute(gemm2_mma,           cudaFuncAttributeMaxDynamicSharedMemorySize, SMG2);

    gemm1_kernel<<<dim3(B_*N_/64, H_), 256>>>(flow_x, Wh);
    graph_bits_kernel<<<128, 256>>>(graph);
    wsplit_kernel<<<128, 256>>>(W_out);
    attn_mma<128,1,128><<<dim3(N_/128, B_, H_), 256, SM1>>>(bh, nullptr);
    gemm2_mma<<<dim3(B_*N_/64), 128, SMG2>>>();
    attn_mma<64,2,64><<<dim3(N_/64, B_, 1), 128, SM2>>>(b_out, out);
}